// round 6
// baseline (speedup 1.0000x reference)
#include <cuda_runtime.h>
#include <cstdint>

// MultiStepIFNode: T=16 integrate-and-fire, pure HBM streaming (256 MiB in,
// 256 MiB out). R1-R5 swept occupancy (87%<->21%), per-thread MLP (2<->16),
// persistent vs waved grids, and read/write grouping: all land at
// 6.29-6.41 TB/s with DRAM traffic exactly at the 512 MiB minimum (no
// write-allocate waste). This is the mixed-stream DRAM ceiling (~80% of
// spec; rest is bus turnaround/refresh).
//
// R6: final granularity tweak on the R5 winner — block 256 -> 128
// (grid 8192): halves the per-CTA LDG batch hitting the L1tex queue and
// doubles CLC work-stealing granularity for wave tails. Everything else
// (16-load front batch, __ldcs/__stcs) unchanged.

static constexpr int T_STEPS = 16;

__global__ __launch_bounds__(128, 4) void if_multistep_kernel(
    const float4* __restrict__ x,   // T * n4 float4s
    float4* __restrict__ out,       // T * n4 float4s
    int n4)                         // float4s per timestep (N/4)
{
    int i = blockIdx.x * blockDim.x + threadIdx.x;
    if (i >= n4) return;

    // Front-batch all 16 loads: one contiguous read burst per thread
    // before any store issues.
    float4 xt[T_STEPS];
    #pragma unroll
    for (int t = 0; t < T_STEPS; t++) {
        xt[t] = __ldcs(&x[(size_t)t * n4 + i]);
    }

    float vx = 0.f, vy = 0.f, vz = 0.f, vw = 0.f;

    #pragma unroll
    for (int t = 0; t < T_STEPS; t++) {
        vx += xt[t].x;
        vy += xt[t].y;
        vz += xt[t].z;
        vw += xt[t].w;

        float4 s;
        s.x = (vx >= 1.0f) ? 1.0f : 0.0f;
        s.y = (vy >= 1.0f) ? 1.0f : 0.0f;
        s.z = (vz >= 1.0f) ? 1.0f : 0.0f;
        s.w = (vw >= 1.0f) ? 1.0f : 0.0f;

        vx -= s.x;
        vy -= s.y;
        vz -= s.z;
        vw -= s.w;

        __stcs(&out[(size_t)t * n4 + i], s);
    }
}

extern "C" void kernel_launch(void* const* d_in, const int* in_sizes, int n_in,
                              void* d_out, int out_size)
{
    const float4* x = (const float4*)d_in[0];
    float4* out = (float4*)d_out;

    int n_per_step = out_size / T_STEPS;   // 4,194,304
    int n4 = n_per_step / 4;               // 1,048,576

    const int threads = 128;
    int blocks = (n4 + threads - 1) / threads;   // 8192
    if_multistep_kernel<<<blocks, threads>>>(x, out, n4);
}